// round 2
// baseline (speedup 1.0000x reference)
#include <cuda_runtime.h>
#include <stdint.h>

// Problem constants
#define BATCH 4
#define SEQ   8192
#define DIM   64
#define NHASH 8
#define NROT  64      // n_buckets/2 : rotation output columns
#define TM    128     // query rows per block

#define SQ_STRIDE 68  // padded row stride for q tile in smem (multiple of 4 for float4 align)

// ---------------------------------------------------------------------------
// Kernel 1: copy v -> out (out = v exactly, see analysis: masked softmax keeps
// only same-position entries whose q/k/v are identical, so o == v and the
// hash-round combine weights sum to 1).
// ---------------------------------------------------------------------------
__global__ void copy_v_kernel(const float4* __restrict__ v, float4* __restrict__ out, int n4)
{
    int i = blockIdx.x * blockDim.x + threadIdx.x;
    int stride = gridDim.x * blockDim.x;
    for (; i < n4; i += stride) out[i] = v[i];
}

// ---------------------------------------------------------------------------
// Kernel 2: LSH hash buckets.
// rotated[b,h,t,i] = sum_f qk[b,t,f] * rot[f,h,i]   (i in [0,64))
// bucket = argmax over [rotated, -rotated] (128 entries, first-occurrence tie)
// output value = bucket + h*128, written as float32 at buckets[(b*8+h)*8192+t]
//
// Block: 128 threads, computes a TM(=128) x 64 tile of `rotated` for one (b,h).
// Thread tile: 8 rows x 8 cols. Thread layout: ct = tid&7 (col group),
// rt = tid>>3 (row group). Per-rt k-rotation makes the scalar q loads
// conflict-free broadcasts.
// ---------------------------------------------------------------------------
__global__ __launch_bounds__(128) void hash_kernel(
    const float* __restrict__ qk,
    const float* __restrict__ rot,          // layout [f=64][h=8][i=64]
    float* __restrict__ out_buckets)
{
    __shared__ float sR[64 * 64];           // sR[k][i]
    __shared__ float sQ[TM * SQ_STRIDE];    // sQ[t][f]

    const int tid = threadIdx.x;
    const int t0  = blockIdx.x * TM;
    const int h   = blockIdx.y;
    const int b   = blockIdx.z;

    // ---- load rotation slice for this h: 64x64 floats ----
    #pragma unroll
    for (int i = tid; i < 1024; i += 128) {
        int f = i >> 4, j = i & 15;
        float4 val = *reinterpret_cast<const float4*>(rot + f * (NHASH * NROT) + h * NROT + j * 4);
        *reinterpret_cast<float4*>(sR + f * 64 + j * 4) = val;
    }

    // ---- load q tile: 128 rows x 64 ----
    const float* qb = qk + ((size_t)b * SEQ + t0) * DIM;
    #pragma unroll
    for (int i = tid; i < 2048; i += 128) {
        int t = i >> 4, j = i & 15;
        float4 val = *reinterpret_cast<const float4*>(qb + t * DIM + j * 4);
        *reinterpret_cast<float4*>(sQ + t * SQ_STRIDE + j * 4) = val;
    }
    __syncthreads();

    const int ct = tid & 7;        // col group: cols [ct*8, ct*8+8)
    const int rt = tid >> 3;       // row group: rows [rt*8, rt*8+8)
    const int kshift = (rt & 7) * 8;

    float acc[8][8];
    #pragma unroll
    for (int r = 0; r < 8; r++)
        #pragma unroll
        for (int c = 0; c < 8; c++) acc[r][c] = 0.0f;

    #pragma unroll 4
    for (int kk = 0; kk < 64; kk++) {
        const int k = (kk + kshift) & 63;
        float a[8];
        #pragma unroll
        for (int r = 0; r < 8; r++)
            a[r] = sQ[(rt * 8 + r) * SQ_STRIDE + k];
        float4 b0 = *reinterpret_cast<const float4*>(sR + k * 64 + ct * 8);
        float4 b1 = *reinterpret_cast<const float4*>(sR + k * 64 + ct * 8 + 4);
        float bb[8] = {b0.x, b0.y, b0.z, b0.w, b1.x, b1.y, b1.z, b1.w};
        #pragma unroll
        for (int r = 0; r < 8; r++)
            #pragma unroll
            for (int c = 0; c < 8; c++)
                acc[r][c] = fmaf(a[r], bb[c], acc[r][c]);
    }

    // ---- signed argmax per row, reduce across the 8 col-group lanes ----
    // argmax over [r_0..r_63, -r_0..-r_63], first occurrence on ties
    // => strict-greater wins; on equal value, smaller index wins.
    #pragma unroll
    for (int r = 0; r < 8; r++) {
        float bv = acc[r][0];
        int   bi = ct * 8;
        #pragma unroll
        for (int c = 1; c < 8; c++) {
            float v = acc[r][c]; int idx = ct * 8 + c;
            if (v > bv || (v == bv && idx < bi)) { bv = v; bi = idx; }
        }
        #pragma unroll
        for (int c = 0; c < 8; c++) {
            float v = -acc[r][c]; int idx = ct * 8 + c + 64;
            if (v > bv || (v == bv && idx < bi)) { bv = v; bi = idx; }
        }
        // reduce across 8 lanes sharing this row group (lane groups of 8)
        #pragma unroll
        for (int m = 1; m < 8; m <<= 1) {
            float ov = __shfl_xor_sync(0xffffffffu, bv, m);
            int   oi = __shfl_xor_sync(0xffffffffu, bi, m);
            if (ov > bv || (ov == bv && oi < bi)) { bv = ov; bi = oi; }
        }
        if (ct == 0) {
            int t = t0 + rt * 8 + r;
            out_buckets[((size_t)b * NHASH + h) * SEQ + t] = (float)(bi + h * 128);
        }
    }
}

// ---------------------------------------------------------------------------
// Launch
// ---------------------------------------------------------------------------
extern "C" void kernel_launch(void* const* d_in, const int* in_sizes, int n_in,
                              void* d_out, int out_size)
{
    const float* qk  = (const float*)d_in[0];   // (4, 8192, 64)
    const float* v   = (const float*)d_in[1];   // (4, 8192, 64)
    const float* rot = (const float*)d_in[2];   // (1, 64, 8, 64)
    float* out = (float*)d_out;

    const int N_OUT = BATCH * SEQ * DIM;        // 2,097,152
    const int N_BKT = BATCH * NHASH * SEQ;      //   262,144

    // Output layout: reference returns (out, buckets). Assume flattened
    // concatenation in tuple order as float32. Branch on out_size so a
    // single-output harness also works.
    int do_out = 1, do_bkt = 1;
    float* out_o = out;
    float* out_b = out + N_OUT;
    if (out_size == N_OUT) {
        do_bkt = 0;
    } else if (out_size == N_BKT) {
        do_out = 0;
        out_b = out;
    }

    if (do_out) {
        int n4 = N_OUT / 4;
        copy_v_kernel<<<1024, 256>>>((const float4*)v, (float4*)out_o, n4);
    }
    if (do_bkt) {
        dim3 grid(SEQ / TM, NHASH, BATCH);      // (64, 8, 4)
        hash_kernel<<<grid, 128>>>(qk, rot, out_b);
    }
}

// round 3
// speedup vs baseline: 1.0255x; 1.0255x over previous
#include <cuda_runtime.h>
#include <stdint.h>

// Problem constants
#define BATCH 4
#define SEQ   8192
#define DIM   64
#define NHASH 8
#define NROT  64      // n_buckets/2 : rotation output columns
#define TM    128     // query rows per block

#define SQ_STRIDE 68  // padded row stride for q tile in smem (multiple of 4 for float4 align)

// ---------------------------------------------------------------------------
// Kernel 1: copy v -> out (out = v exactly, see analysis: masked softmax keeps
// only same-position entries whose q/k/v are identical, so o == v and the
// hash-round combine weights sum to 1).
// ---------------------------------------------------------------------------
__global__ void copy_v_kernel(const float4* __restrict__ v, float4* __restrict__ out, int n4)
{
    int i = blockIdx.x * blockDim.x + threadIdx.x;
    int stride = gridDim.x * blockDim.x;
    for (; i < n4; i += stride) out[i] = v[i];
}

// ---------------------------------------------------------------------------
// Kernel 2: LSH hash buckets.
// rotated[b,h,t,i] = sum_f qk[b,t,f] * rot[f,h,i]   (i in [0,64))
// bucket = argmax over [rotated, -rotated] (128 entries, first-occurrence tie)
// output value = bucket + h*128, written as float32 at buckets[(b*8+h)*8192+t]
//
// Block: 128 threads, computes a TM(=128) x 64 tile of `rotated` for one (b,h).
// Thread tile: 8 rows x 8 cols. Thread layout: ct = tid&7 (col group),
// rt = tid>>3 (row group). Per-rt k-rotation makes the scalar q loads
// conflict-free broadcasts.
// ---------------------------------------------------------------------------
__global__ __launch_bounds__(128) void hash_kernel(
    const float* __restrict__ qk,
    const float* __restrict__ rot,          // layout [f=64][h=8][i=64]
    float* __restrict__ out_buckets)
{
    __shared__ float sR[64 * 64];           // sR[k][i]
    __shared__ float sQ[TM * SQ_STRIDE];    // sQ[t][f]

    const int tid = threadIdx.x;
    const int t0  = blockIdx.x * TM;
    const int h   = blockIdx.y;
    const int b   = blockIdx.z;

    // ---- load rotation slice for this h: 64x64 floats ----
    #pragma unroll
    for (int i = tid; i < 1024; i += 128) {
        int f = i >> 4, j = i & 15;
        float4 val = *reinterpret_cast<const float4*>(rot + f * (NHASH * NROT) + h * NROT + j * 4);
        *reinterpret_cast<float4*>(sR + f * 64 + j * 4) = val;
    }

    // ---- load q tile: 128 rows x 64 ----
    const float* qb = qk + ((size_t)b * SEQ + t0) * DIM;
    #pragma unroll
    for (int i = tid; i < 2048; i += 128) {
        int t = i >> 4, j = i & 15;
        float4 val = *reinterpret_cast<const float4*>(qb + t * DIM + j * 4);
        *reinterpret_cast<float4*>(sQ + t * SQ_STRIDE + j * 4) = val;
    }
    __syncthreads();

    const int ct = tid & 7;        // col group: cols [ct*8, ct*8+8)
    const int rt = tid >> 3;       // row group: rows [rt*8, rt*8+8)
    const int kshift = (rt & 7) * 8;

    float acc[8][8];
    #pragma unroll
    for (int r = 0; r < 8; r++)
        #pragma unroll
        for (int c = 0; c < 8; c++) acc[r][c] = 0.0f;

    #pragma unroll 4
    for (int kk = 0; kk < 64; kk++) {
        const int k = (kk + kshift) & 63;
        float a[8];
        #pragma unroll
        for (int r = 0; r < 8; r++)
            a[r] = sQ[(rt * 8 + r) * SQ_STRIDE + k];
        float4 b0 = *reinterpret_cast<const float4*>(sR + k * 64 + ct * 8);
        float4 b1 = *reinterpret_cast<const float4*>(sR + k * 64 + ct * 8 + 4);
        float bb[8] = {b0.x, b0.y, b0.z, b0.w, b1.x, b1.y, b1.z, b1.w};
        #pragma unroll
        for (int r = 0; r < 8; r++)
            #pragma unroll
            for (int c = 0; c < 8; c++)
                acc[r][c] = fmaf(a[r], bb[c], acc[r][c]);
    }

    // ---- signed argmax per row, reduce across the 8 col-group lanes ----
    // argmax over [r_0..r_63, -r_0..-r_63], first occurrence on ties
    // => strict-greater wins; on equal value, smaller index wins.
    #pragma unroll
    for (int r = 0; r < 8; r++) {
        float bv = acc[r][0];
        int   bi = ct * 8;
        #pragma unroll
        for (int c = 1; c < 8; c++) {
            float v = acc[r][c]; int idx = ct * 8 + c;
            if (v > bv || (v == bv && idx < bi)) { bv = v; bi = idx; }
        }
        #pragma unroll
        for (int c = 0; c < 8; c++) {
            float v = -acc[r][c]; int idx = ct * 8 + c + 64;
            if (v > bv || (v == bv && idx < bi)) { bv = v; bi = idx; }
        }
        // reduce across 8 lanes sharing this row group (lane groups of 8)
        #pragma unroll
        for (int m = 1; m < 8; m <<= 1) {
            float ov = __shfl_xor_sync(0xffffffffu, bv, m);
            int   oi = __shfl_xor_sync(0xffffffffu, bi, m);
            if (ov > bv || (ov == bv && oi < bi)) { bv = ov; bi = oi; }
        }
        if (ct == 0) {
            int t = t0 + rt * 8 + r;
            out_buckets[((size_t)b * NHASH + h) * SEQ + t] = (float)(bi + h * 128);
        }
    }
}

// ---------------------------------------------------------------------------
// Launch
// ---------------------------------------------------------------------------
extern "C" void kernel_launch(void* const* d_in, const int* in_sizes, int n_in,
                              void* d_out, int out_size)
{
    const float* qk  = (const float*)d_in[0];   // (4, 8192, 64)
    const float* v   = (const float*)d_in[1];   // (4, 8192, 64)
    const float* rot = (const float*)d_in[2];   // (1, 64, 8, 64)
    float* out = (float*)d_out;

    const int N_OUT = BATCH * SEQ * DIM;        // 2,097,152
    const int N_BKT = BATCH * NHASH * SEQ;      //   262,144

    // Output layout: reference returns (out, buckets). Assume flattened
    // concatenation in tuple order as float32. Branch on out_size so a
    // single-output harness also works.
    int do_out = 1, do_bkt = 1;
    float* out_o = out;
    float* out_b = out + N_OUT;
    if (out_size == N_OUT) {
        do_bkt = 0;
    } else if (out_size == N_BKT) {
        do_out = 0;
        out_b = out;
    }

    if (do_out) {
        int n4 = N_OUT / 4;
        copy_v_kernel<<<1024, 256>>>((const float4*)v, (float4*)out_o, n4);
    }
    if (do_bkt) {
        dim3 grid(SEQ / TM, NHASH, BATCH);      // (64, 8, 4)
        hash_kernel<<<grid, 128>>>(qk, rot, out_b);
    }
}